// round 12
// baseline (speedup 1.0000x reference)
#include <cuda_runtime.h>
#include <cuda_fp16.h>
#include <cstdint>
#include <math.h>

// ---------------- problem constants ----------------
#define BATCH 8192
#define IN_F  1024
#define OUT_F 1024
#define NB    8
#define KTOT  9216                       // 1024 (silu) + 8192 (basis)

// ---------------- GEMM tiling (fp16 HMMA m16n8k16) ----------------
#define BM 128
#define BN 256
#define BK 64                            // 64 halfs = 128 bytes = one SW128 row
#define STAGES 4
#define NITER (KTOT / BK)                // 144
#define STAGE_BYTES ((BM + BN) * 128)    // 49152
#define BB_OFF (BM * 128)                // 16384
#define SMEM_DYN (STAGES * STAGE_BYTES)  // 196608

// scratch (allocation-free rule: __device__ globals)
__device__ __half g_A[(size_t)BATCH * KTOT];   // 151 MB  (full fused A)
__device__ __half g_W[(size_t)OUT_F * KTOT];   //  19 MB

// ---------------- helpers ----------------
__device__ __forceinline__ uint32_t smem_u32(const void* p) {
    uint32_t a;
    asm("{ .reg .u64 t; cvta.to.shared.u64 t, %1; cvt.u32.u64 %0, t; }" : "=r"(a) : "l"(p));
    return a;
}

#define SWZ(o) ((o) ^ (((o) >> 3) & 0x70))

__device__ __forceinline__ void cp16(uint32_t dst, const void* src) {
    asm volatile("cp.async.cg.shared.global [%0], [%1], 16;"
                 :: "r"(dst), "l"(__cvta_generic_to_global(src)));
}
#define CP_COMMIT() asm volatile("cp.async.commit_group;" ::: "memory")
#define CP_WAIT_2() asm volatile("cp.async.wait_group 2;" ::: "memory")

#define LDSM4(r, addr) \
    asm volatile("ldmatrix.sync.aligned.m8n8.x4.shared.b16 {%0,%1,%2,%3}, [%4];" \
        : "=r"((r)[0]), "=r"((r)[1]), "=r"((r)[2]), "=r"((r)[3]) : "r"(addr))

// m16n8k16 fp16 MMA, fp32 accumulate (sm_80+ baseline — legal on plain sm_103)
__device__ __forceinline__ void mma_f16(float* c, const uint32_t* a,
                                        uint32_t b0, uint32_t b1) {
    asm volatile(
        "mma.sync.aligned.m16n8k16.row.col.f32.f16.f16.f32 "
        "{%0,%1,%2,%3}, {%4,%5,%6,%7}, {%8,%9}, {%0,%1,%2,%3};"
        : "+f"(c[0]), "+f"(c[1]), "+f"(c[2]), "+f"(c[3])
        : "r"(a[0]), "r"(a[1]), "r"(a[2]), "r"(a[3]), "r"(b0), "r"(b1));
}

// FMA-only SiLU. exp(-|v|) via range reduction + deg-4 2^u poly + exponent
// splice; 1/(1+e) via Newton, seed valid on d in [1,2]: r0 = 24/17 - 8/17*d.
__device__ __forceinline__ float silu_fma(float v) {
    float av = fminf(fabsf(v), 80.0f);
    float y = av * 1.4426950408889634f;          // av * log2(e)
    float n = floorf(y + 0.5f);
    float u = n - y;                             // [-0.5,0.5]; 2^{-y} = 2^u * 2^{-n}
    float p = fmaf(u, 0.0096181291f, 0.0555041087f);
    p = fmaf(u, p, 0.2402265069f);
    p = fmaf(u, p, 0.6931471806f);
    p = fmaf(u, p, 1.0f);                        // 2^u
    float s = __int_as_float((127 - (int)n) << 23);  // 2^{-n}
    float e = p * s;                             // exp(-av), (0,1]
    float d = 1.0f + e;                          // (1,2]
    float r = fmaf(d, -0.470588235f, 1.411764706f);  // 24/17 - 8/17*d
    r = r * (2.0f - d * r);
    r = r * (2.0f - d * r);                      // 1/(1+e)
    float sig = (v >= 0.0f) ? r : (1.0f - r);
    return v * sig;
}

// Cubic B-spline: fill one 8-half basis chunk for a single x value.
__device__ __forceinline__ void basis_chunk(float v, __half* h) {
    float xc = fminf(fmaxf(v, -1.0f), 1.0f);
    int seg = min((int)floorf((xc + 1.0f) * 2.5f), 5);
    float t = fmaf(2.5f, xc, 2.5f - (float)seg);     // in [0,1]
    float t2 = t * t, t3 = t2 * t;
    float omt = 1.0f - t;
    const float c6 = 1.0f / 6.0f;
    float w0 = omt * omt * omt * c6;
    float w1 = (3.0f * t3 - 6.0f * t2 + 4.0f) * c6;
    float w2 = (-3.0f * t3 + 3.0f * t2 + 3.0f * t + 1.0f) * c6;
    float w3 = t3 * c6;
#pragma unroll
    for (int j = 0; j < 8; j++) h[j] = __ushort_as_half((unsigned short)0);
    h[seg]     = __float2half_rn(w0);
    h[seg + 1] = __float2half_rn(w1);
    h[seg + 2] = __float2half_rn(w2);
    if (seg + 3 < 8) h[seg + 3] = __float2half_rn(w3);   // seg==5: w3==0, slot absent
}

// =====================================================================
// P0: g_A = [ h(silu(x)) | h(cubic basis(clip(x))) ], 8 x-values/thread.
// Per thread: 32B read, 16B silu store, 128B contiguous basis store.
// =====================================================================
__global__ void prep_A_kernel(const float* __restrict__ x) {
    size_t t8 = ((size_t)blockIdx.x * blockDim.x + threadIdx.x) * 8;  // linear elem idx
    int b  = (int)(t8 >> 10);        // /1024
    int i0 = (int)(t8 & 1023);       // multiple of 8
    const float* src = x + t8;
    float4 f0 = *(const float4*)(src);
    float4 f1 = *(const float4*)(src + 4);
    float xv[8] = {f0.x, f0.y, f0.z, f0.w, f1.x, f1.y, f1.z, f1.w};

    __half* row = g_A + (size_t)b * KTOT;

    // silu: 8 halfs = one 16B store
    __half hs[8];
#pragma unroll
    for (int q = 0; q < 8; q++) hs[q] = __float2half_rn(silu_fma(xv[q]));
    *(uint4*)(row + i0) = *(const uint4*)hs;

    // basis: 8 chunks x 16B = 128B contiguous
    __half hb[64];
#pragma unroll
    for (int q = 0; q < 8; q++) basis_chunk(xv[q], hb + q * 8);
    uint4* dst = (uint4*)(row + IN_F + (size_t)i0 * NB);
#pragma unroll
    for (int q = 0; q < 8; q++) dst[q] = ((const uint4*)hb)[q];
}

// =====================================================================
// P1: W = [ h(base_weight) | h(spline_weight) ]  (O, 9216), 8 elems/thread
// =====================================================================
__global__ void prep_W_kernel(const float* __restrict__ bw, const float* __restrict__ sw) {
    int o = blockIdx.y;
    int k8 = (blockIdx.x * blockDim.x + threadIdx.x) * 8;
    const float* src = (k8 < IN_F) ? (bw + (size_t)o * IN_F + k8)
                                   : (sw + (size_t)o * (IN_F * NB) + (k8 - IN_F));
    float4 f0 = *(const float4*)(src);
    float4 f1 = *(const float4*)(src + 4);
    __half h[8];
    h[0] = __float2half_rn(f0.x); h[1] = __float2half_rn(f0.y);
    h[2] = __float2half_rn(f0.z); h[3] = __float2half_rn(f0.w);
    h[4] = __float2half_rn(f1.x); h[5] = __float2half_rn(f1.y);
    h[6] = __float2half_rn(f1.z); h[7] = __float2half_rn(f1.w);
    *(uint4*)(g_W + (size_t)o * KTOT + k8) = *(const uint4*)h;
}

// =====================================================================
// GEMM: out[m,n] = sum_k A[m,k] * W[n,k]
// fp16 m16n8k16, BM=128 x BN=256, 8 warps (2x4), warp tile 64x64,
// 4-stage cp.async pipeline + double-buffered ldmatrix fragments.
// (Unchanged from R11 best-passing kernel.)
// =====================================================================
__global__ __launch_bounds__(256, 1)
void kan_gemm_kernel(float* __restrict__ out) {
    extern __shared__ char smem[];
    uint32_t sb = smem_u32(smem);
    int tid = threadIdx.x;
    int wid = tid >> 5;
    int lid = tid & 31;
    int n0 = blockIdx.x * BN;
    int m0 = blockIdx.y * BM;

    // ---- producer addressing: 12 x 16B chunks / thread / stage ----
    int rb = tid >> 3, cb = tid & 7;
    size_t aoff = (size_t)(m0 + rb) * KTOT + cb * 8;     // halfs
    size_t boff = (size_t)(n0 + rb) * KTOT + cb * 8;
    uint32_t s0 = SWZ((uint32_t)(rb * 128 + cb * 16));   // +4096 per 32 rows (swizzle-safe)

    auto load_stage = [&](int L) {
        uint32_t base = sb + (uint32_t)(L & (STAGES - 1)) * STAGE_BYTES;
        size_t kb = (size_t)L * BK;
#pragma unroll
        for (int u = 0; u < 4; u++)                      // A: 128 rows x 8 chunks
            cp16(base + s0 + u * 4096, g_A + aoff + (size_t)u * 32 * KTOT + kb);
#pragma unroll
        for (int u = 0; u < 8; u++)                      // B: 256 rows x 8 chunks
            cp16(base + BB_OFF + s0 + u * 4096, g_W + boff + (size_t)u * 32 * KTOT + kb);
    };

    // ---- consumer addressing ----
    int wm = (wid >> 2) * 64;
    int wn = (wid & 3) * 64;
    int arow = ((lid & 8) ? 8 : 0) + (lid & 7);
    int akg  = (lid & 16) ? 16 : 0;
    int brow = ((lid & 16) ? 8 : 0) + (lid & 7);
    int bkg  = (lid & 8) ? 16 : 0;

    float acc[4][8][4];
#pragma unroll
    for (int mi = 0; mi < 4; mi++)
#pragma unroll
        for (int ni = 0; ni < 8; ni++)
#pragma unroll
            for (int v = 0; v < 4; v++) acc[mi][ni][v] = 0.0f;

    uint32_t af[2][4][4], bf[2][4][4];

    // ---- pipeline ----
    load_stage(0); CP_COMMIT();
    load_stage(1); CP_COMMIT();
    load_stage(2); CP_COMMIT();

    for (int i = 0; i < NITER; i++) {
        CP_WAIT_2();                 // stage i resident (this thread's copies)
        __syncthreads();             // all copies visible; buf (i-1)%4 reads done
        if (i + 3 < NITER) load_stage(i + 3);
        CP_COMMIT();                 // uniform group count

        uint32_t stg = sb + (uint32_t)(i & 3) * STAGE_BYTES;

        // prime fragments for s=0
#pragma unroll
        for (int mi = 0; mi < 4; mi++)
            LDSM4(af[0][mi], stg + SWZ((uint32_t)((wm + mi * 16 + arow) * 128 + akg)));
#pragma unroll
        for (int p = 0; p < 4; p++)
            LDSM4(bf[0][p], stg + BB_OFF + SWZ((uint32_t)((wn + p * 16 + brow) * 128 + bkg)));

#pragma unroll
        for (int s = 0; s < 4; s++) {            // 4 x k16 steps = BK 64
            int cur = s & 1, nxt = cur ^ 1;
            if (s < 3) {                          // prefetch s+1 before s's MMAs
#pragma unroll
                for (int mi = 0; mi < 4; mi++)
                    LDSM4(af[nxt][mi], stg + SWZ((uint32_t)((wm + mi * 16 + arow) * 128
                                                            + (s + 1) * 32 + akg)));
#pragma unroll
                for (int p = 0; p < 4; p++)
                    LDSM4(bf[nxt][p], stg + BB_OFF + SWZ((uint32_t)((wn + p * 16 + brow) * 128
                                                                    + (s + 1) * 32 + bkg)));
            }
#pragma unroll
            for (int mi = 0; mi < 4; mi++)
#pragma unroll
                for (int ni = 0; ni < 8; ni++)
                    mma_f16(acc[mi][ni], af[cur][mi],
                            bf[cur][ni >> 1][(ni & 1) * 2], bf[cur][ni >> 1][(ni & 1) * 2 + 1]);
        }
    }

    // ---- epilogue: c frag m16n8 f32: rows {t/4, t/4+8}, cols {2*(t%4), +1} ----
    int er = m0 + wm + (lid >> 2);
    int ec = n0 + wn + (lid & 3) * 2;
#pragma unroll
    for (int mi = 0; mi < 4; mi++) {
#pragma unroll
        for (int ni = 0; ni < 8; ni++) {
            float2 v0 = make_float2(acc[mi][ni][0], acc[mi][ni][1]);
            float2 v1 = make_float2(acc[mi][ni][2], acc[mi][ni][3]);
            *(float2*)(out + (size_t)(er + mi * 16) * OUT_F + ec + ni * 8) = v0;
            *(float2*)(out + (size_t)(er + mi * 16 + 8) * OUT_F + ec + ni * 8) = v1;
        }
    }
}

// =====================================================================
extern "C" void kernel_launch(void* const* d_in, const int* in_sizes, int n_in,
                              void* d_out, int out_size) {
    const float* x  = (const float*)d_in[0];   // (8192, 1024)
    const float* bw = (const float*)d_in[1];   // (1024, 1024)
    const float* sw = (const float*)d_in[2];   // (1024, 1024, 8)
    float* out = (float*)d_out;                // (8192, 1024)

    prep_A_kernel<<<(BATCH * IN_F / 8) / 256, 256>>>(x);
    prep_W_kernel<<<dim3(KTOT / 8 / 128, OUT_F), 128>>>(bw, sw);

    cudaFuncSetAttribute(kan_gemm_kernel, cudaFuncAttributeMaxDynamicSharedMemorySize, SMEM_DYN);
    kan_gemm_kernel<<<dim3(OUT_F / BN, BATCH / BM), 256, SMEM_DYN>>>(out);
}

// round 13
// speedup vs baseline: 1.1099x; 1.1099x over previous
#include <cuda_runtime.h>
#include <cuda_fp16.h>
#include <cstdint>
#include <math.h>

// ---------------- problem constants ----------------
#define BATCH 8192
#define IN_F  1024
#define OUT_F 1024
#define NB    8
#define KTOT  9216                       // 1024 (silu) + 8192 (basis)

// ---------------- GEMM tiling (fp16 HMMA m16n8k16) ----------------
#define BM 128
#define BN 256
#define BK 64                            // 64 halfs = 128 bytes = one SW128 row
#define STAGES 4
#define NITER (KTOT / BK)                // 144
#define STAGE_BYTES ((BM + BN) * 128)    // 49152
#define BB_OFF (BM * 128)                // 16384
#define SMEM_DYN (STAGES * STAGE_BYTES)  // 196608

// scratch (allocation-free rule: __device__ globals)
__device__ __half g_A[(size_t)BATCH * KTOT];   // 151 MB  (full fused A)
__device__ __half g_W[(size_t)OUT_F * KTOT];   //  19 MB

// ---------------- helpers ----------------
__device__ __forceinline__ uint32_t smem_u32(const void* p) {
    uint32_t a;
    asm("{ .reg .u64 t; cvta.to.shared.u64 t, %1; cvt.u32.u64 %0, t; }" : "=r"(a) : "l"(p));
    return a;
}

#define SWZ(o) ((o) ^ (((o) >> 3) & 0x70))

__device__ __forceinline__ void cp16(uint32_t dst, const void* src) {
    asm volatile("cp.async.cg.shared.global [%0], [%1], 16;"
                 :: "r"(dst), "l"(__cvta_generic_to_global(src)));
}
#define CP_COMMIT() asm volatile("cp.async.commit_group;" ::: "memory")
#define CP_WAIT_2() asm volatile("cp.async.wait_group 2;" ::: "memory")

#define LDSM4(r, addr) \
    asm volatile("ldmatrix.sync.aligned.m8n8.x4.shared.b16 {%0,%1,%2,%3}, [%4];" \
        : "=r"((r)[0]), "=r"((r)[1]), "=r"((r)[2]), "=r"((r)[3]) : "r"(addr))

// m16n8k16 fp16 MMA, fp32 accumulate (sm_80+ baseline — legal on plain sm_103)
__device__ __forceinline__ void mma_f16(float* c, const uint32_t* a,
                                        uint32_t b0, uint32_t b1) {
    asm volatile(
        "mma.sync.aligned.m16n8k16.row.col.f32.f16.f16.f32 "
        "{%0,%1,%2,%3}, {%4,%5,%6,%7}, {%8,%9}, {%0,%1,%2,%3};"
        : "+f"(c[0]), "+f"(c[1]), "+f"(c[2]), "+f"(c[3])
        : "r"(a[0]), "r"(a[1]), "r"(a[2]), "r"(a[3]), "r"(b0), "r"(b1));
}

// FMA-only SiLU. exp(-|v|) via range reduction + deg-4 2^u poly + exponent
// splice; 1/(1+e) via Newton, seed valid on d in [1,2]: r0 = 24/17 - 8/17*d.
__device__ __forceinline__ float silu_fma(float v) {
    float av = fminf(fabsf(v), 80.0f);
    float y = av * 1.4426950408889634f;          // av * log2(e)
    float n = floorf(y + 0.5f);
    float u = n - y;                             // [-0.5,0.5]; 2^{-y} = 2^u * 2^{-n}
    float p = fmaf(u, 0.0096181291f, 0.0555041087f);
    p = fmaf(u, p, 0.2402265069f);
    p = fmaf(u, p, 0.6931471806f);
    p = fmaf(u, p, 1.0f);                        // 2^u
    float s = __int_as_float((127 - (int)n) << 23);  // 2^{-n}
    float e = p * s;                             // exp(-av), (0,1]
    float d = 1.0f + e;                          // (1,2]
    float r = fmaf(d, -0.470588235f, 1.411764706f);  // 24/17 - 8/17*d
    r = r * (2.0f - d * r);
    r = r * (2.0f - d * r);                      // 1/(1+e)
    float sig = (v >= 0.0f) ? r : (1.0f - r);
    return v * sig;
}

// Cubic B-spline basis chunk -> 4 packed uint32 (8 halfs), branch-free,
// register-only (NO dynamic array indexing -> no local-memory demotion).
// Slot j gets w[j-seg] for j-seg in 0..3, else 0. seg==5: slot 8 out of
// range, w3 (==0 at t==0) naturally dropped — matches reference semantics.
__device__ __forceinline__ void basis_chunk_packed(float v, uint32_t* r) {
    float xc = fminf(fmaxf(v, -1.0f), 1.0f);
    int seg = min((int)floorf((xc + 1.0f) * 2.5f), 5);
    float t = fmaf(2.5f, xc, 2.5f - (float)seg);     // in [0,1]
    float t2 = t * t, t3 = t2 * t;
    float omt = 1.0f - t;
    const float c6 = 1.0f / 6.0f;
    float w0 = omt * omt * omt * c6;
    float w1 = (3.0f * t3 - 6.0f * t2 + 4.0f) * c6;
    float w2 = (-3.0f * t3 + 3.0f * t2 + 3.0f * t + 1.0f) * c6;
    float w3 = t3 * c6;

    uint32_t b0 = (uint32_t)__half_as_ushort(__float2half_rn(w0));
    uint32_t b1 = (uint32_t)__half_as_ushort(__float2half_rn(w1));
    uint32_t b2 = (uint32_t)__half_as_ushort(__float2half_rn(w2));
    uint32_t b3 = (uint32_t)__half_as_ushort(__float2half_rn(w3));

    uint32_t u[8];
#pragma unroll
    for (int j = 0; j < 8; j++) {
        int idx = j - seg;
        uint32_t val = 0;
        val = (idx == 0) ? b0 : val;
        val = (idx == 1) ? b1 : val;
        val = (idx == 2) ? b2 : val;
        val = (idx == 3) ? b3 : val;
        u[j] = val;                                   // static index -> registers
    }
#pragma unroll
    for (int pjj = 0; pjj < 4; pjj++)
        r[pjj] = u[2 * pjj] | (u[2 * pjj + 1] << 16);
}

// =====================================================================
// P0: g_A = [ h(silu(x)) | h(cubic basis(clip(x))) ], 8 x-values/thread.
// Per thread: 32B read, 16B silu store, 128B contiguous basis store.
// All intermediates in registers (select-chain basis, no spills).
// =====================================================================
__global__ void prep_A_kernel(const float* __restrict__ x) {
    size_t t8 = ((size_t)blockIdx.x * blockDim.x + threadIdx.x) * 8;  // linear elem idx
    int b  = (int)(t8 >> 10);        // /1024
    int i0 = (int)(t8 & 1023);       // multiple of 8
    const float* src = x + t8;
    float4 f0 = *(const float4*)(src);
    float4 f1 = *(const float4*)(src + 4);
    float xv[8] = {f0.x, f0.y, f0.z, f0.w, f1.x, f1.y, f1.z, f1.w};

    __half* row = g_A + (size_t)b * KTOT;

    // silu: 8 halfs packed into one 16B store
    uint32_t hs[4];
#pragma unroll
    for (int q = 0; q < 4; q++) {
        uint32_t lo = (uint32_t)__half_as_ushort(__float2half_rn(silu_fma(xv[2 * q])));
        uint32_t hi = (uint32_t)__half_as_ushort(__float2half_rn(silu_fma(xv[2 * q + 1])));
        hs[q] = lo | (hi << 16);
    }
    *(uint4*)(row + i0) = make_uint4(hs[0], hs[1], hs[2], hs[3]);

    // basis: 8 chunks x 16B = 128B contiguous, all register-resident
    uint4* dst = (uint4*)(row + IN_F + (size_t)i0 * NB);
#pragma unroll
    for (int q = 0; q < 8; q++) {
        uint32_t rc[4];
        basis_chunk_packed(xv[q], rc);
        dst[q] = make_uint4(rc[0], rc[1], rc[2], rc[3]);
    }
}

// =====================================================================
// P1: W = [ h(base_weight) | h(spline_weight) ]  (O, 9216), 8 elems/thread
// =====================================================================
__global__ void prep_W_kernel(const float* __restrict__ bw, const float* __restrict__ sw) {
    int o = blockIdx.y;
    int k8 = (blockIdx.x * blockDim.x + threadIdx.x) * 8;
    const float* src = (k8 < IN_F) ? (bw + (size_t)o * IN_F + k8)
                                   : (sw + (size_t)o * (IN_F * NB) + (k8 - IN_F));
    float4 f0 = *(const float4*)(src);
    float4 f1 = *(const float4*)(src + 4);
    __half h[8];
    h[0] = __float2half_rn(f0.x); h[1] = __float2half_rn(f0.y);
    h[2] = __float2half_rn(f0.z); h[3] = __float2half_rn(f0.w);
    h[4] = __float2half_rn(f1.x); h[5] = __float2half_rn(f1.y);
    h[6] = __float2half_rn(f1.z); h[7] = __float2half_rn(f1.w);
    *(uint4*)(g_W + (size_t)o * KTOT + k8) = *(const uint4*)h;
}

// =====================================================================
// GEMM: out[m,n] = sum_k A[m,k] * W[n,k]
// fp16 m16n8k16, BM=128 x BN=256, 8 warps (2x4), warp tile 64x64,
// 4-stage cp.async pipeline + double-buffered ldmatrix fragments.
// (Unchanged from R11 best-passing kernel.)
// =====================================================================
__global__ __launch_bounds__(256, 1)
void kan_gemm_kernel(float* __restrict__ out) {
    extern __shared__ char smem[];
    uint32_t sb = smem_u32(smem);
    int tid = threadIdx.x;
    int wid = tid >> 5;
    int lid = tid & 31;
    int n0 = blockIdx.x * BN;
    int m0 = blockIdx.y * BM;

    // ---- producer addressing: 12 x 16B chunks / thread / stage ----
    int rb = tid >> 3, cb = tid & 7;
    size_t aoff = (size_t)(m0 + rb) * KTOT + cb * 8;     // halfs
    size_t boff = (size_t)(n0 + rb) * KTOT + cb * 8;
    uint32_t s0 = SWZ((uint32_t)(rb * 128 + cb * 16));   // +4096 per 32 rows (swizzle-safe)

    auto load_stage = [&](int L) {
        uint32_t base = sb + (uint32_t)(L & (STAGES - 1)) * STAGE_BYTES;
        size_t kb = (size_t)L * BK;
#pragma unroll
        for (int u = 0; u < 4; u++)                      // A: 128 rows x 8 chunks
            cp16(base + s0 + u * 4096, g_A + aoff + (size_t)u * 32 * KTOT + kb);
#pragma unroll
        for (int u = 0; u < 8; u++)                      // B: 256 rows x 8 chunks
            cp16(base + BB_OFF + s0 + u * 4096, g_W + boff + (size_t)u * 32 * KTOT + kb);
    };

    // ---- consumer addressing ----
    int wm = (wid >> 2) * 64;
    int wn = (wid & 3) * 64;
    int arow = ((lid & 8) ? 8 : 0) + (lid & 7);
    int akg  = (lid & 16) ? 16 : 0;
    int brow = ((lid & 16) ? 8 : 0) + (lid & 7);
    int bkg  = (lid & 8) ? 16 : 0;

    float acc[4][8][4];
#pragma unroll
    for (int mi = 0; mi < 4; mi++)
#pragma unroll
        for (int ni = 0; ni < 8; ni++)
#pragma unroll
            for (int v = 0; v < 4; v++) acc[mi][ni][v] = 0.0f;

    uint32_t af[2][4][4], bf[2][4][4];

    // ---- pipeline ----
    load_stage(0); CP_COMMIT();
    load_stage(1); CP_COMMIT();
    load_stage(2); CP_COMMIT();

    for (int i = 0; i < NITER; i++) {
        CP_WAIT_2();                 // stage i resident (this thread's copies)
        __syncthreads();             // all copies visible; buf (i-1)%4 reads done
        if (i + 3 < NITER) load_stage(i + 3);
        CP_COMMIT();                 // uniform group count

        uint32_t stg = sb + (uint32_t)(i & 3) * STAGE_BYTES;

        // prime fragments for s=0
#pragma unroll
        for (int mi = 0; mi < 4; mi++)
            LDSM4(af[0][mi], stg + SWZ((uint32_t)((wm + mi * 16 + arow) * 128 + akg)));
#pragma unroll
        for (int p = 0; p < 4; p++)
            LDSM4(bf[0][p], stg + BB_OFF + SWZ((uint32_t)((wn + p * 16 + brow) * 128 + bkg)));

#pragma unroll
        for (int s = 0; s < 4; s++) {            // 4 x k16 steps = BK 64
            int cur = s & 1, nxt = cur ^ 1;
            if (s < 3) {                          // prefetch s+1 before s's MMAs
#pragma unroll
                for (int mi = 0; mi < 4; mi++)
                    LDSM4(af[nxt][mi], stg + SWZ((uint32_t)((wm + mi * 16 + arow) * 128
                                                            + (s + 1) * 32 + akg)));
#pragma unroll
                for (int p = 0; p < 4; p++)
                    LDSM4(bf[nxt][p], stg + BB_OFF + SWZ((uint32_t)((wn + p * 16 + brow) * 128
                                                                    + (s + 1) * 32 + bkg)));
            }
#pragma unroll
            for (int mi = 0; mi < 4; mi++)
#pragma unroll
                for (int ni = 0; ni < 8; ni++)
                    mma_f16(acc[mi][ni], af[cur][mi],
                            bf[cur][ni >> 1][(ni & 1) * 2], bf[cur][ni >> 1][(ni & 1) * 2 + 1]);
        }
    }

    // ---- epilogue: c frag m16n8 f32: rows {t/4, t/4+8}, cols {2*(t%4), +1} ----
    int er = m0 + wm + (lid >> 2);
    int ec = n0 + wn + (lid & 3) * 2;
#pragma unroll
    for (int mi = 0; mi < 4; mi++) {
#pragma unroll
        for (int ni = 0; ni < 8; ni++) {
            float2 v0 = make_float2(acc[mi][ni][0], acc[mi][ni][1]);
            float2 v1 = make_float2(acc[mi][ni][2], acc[mi][ni][3]);
            *(float2*)(out + (size_t)(er + mi * 16) * OUT_F + ec + ni * 8) = v0;
            *(float2*)(out + (size_t)(er + mi * 16 + 8) * OUT_F + ec + ni * 8) = v1;
        }
    }
}

// =====================================================================
extern "C" void kernel_launch(void* const* d_in, const int* in_sizes, int n_in,
                              void* d_out, int out_size) {
    const float* x  = (const float*)d_in[0];   // (8192, 1024)
    const float* bw = (const float*)d_in[1];   // (1024, 1024)
    const float* sw = (const float*)d_in[2];   // (1024, 1024, 8)
    float* out = (float*)d_out;                // (8192, 1024)

    prep_A_kernel<<<(BATCH * IN_F / 8) / 256, 256>>>(x);
    prep_W_kernel<<<dim3(KTOT / 8 / 128, OUT_F), 128>>>(bw, sw);

    cudaFuncSetAttribute(kan_gemm_kernel, cudaFuncAttributeMaxDynamicSharedMemorySize, SMEM_DYN);
    kan_gemm_kernel<<<dim3(OUT_F / BN, BATCH / BM), 256, SMEM_DYN>>>(out);
}